// round 2
// baseline (speedup 1.0000x reference)
#include <cuda_runtime.h>

// RiRoIAlign for GB300 — vectorized bilinear taps.
// features: (B=2, Ctot=256, H=256, W=256) fp32
// rois: (512, 6) fp32 = [batch, cx, cy, w, h, theta]
// out: (512, 256, 7, 7) fp32, channel = c*8 + o  (C=32, O=8)
//
// Per sample, the two x-taps (x_low, x_low+1) are fetched with ONE aligned
// float4 load; the x-weights are baked into a float4 so the bilinear x-mix is
// a dot product. Only samples with (x_low & 3)==3 need a scalar tail load
// (this also covers the W-1 edge clamp, since 255 % 4 == 3).

#define HH 256
#define WW 256
#define CT 256
#define OO 8
#define NBIN 49
#define NS 196
#define HW (HH * WW)

__global__ __launch_bounds__(256, 3)
void riroi_kernel(const float* __restrict__ features,
                  const float* __restrict__ rois,
                  float* __restrict__ out)
{
    __shared__ int4   sidx[NS];   // rowL(=y_low*W), rowH(=y_high*W), xq4(=(x_low>>2)*4), xh
    __shared__ float4 swx[NS];    // x-weight vector for the float4
    __shared__ float4 swy[NS];    // {hy*vm, ly*vm, w_extra, 0}
    __shared__ float  acc[OO * NBIN];

    const int r   = blockIdx.x;
    const int cg  = blockIdx.y;
    const int tid = threadIdx.x;

    const float b_f = rois[r * 6 + 0];
    const float cwv = rois[r * 6 + 1] * 0.125f;
    const float chv = rois[r * 6 + 2] * 0.125f;
    const float rw  = fmaxf(rois[r * 6 + 3] * 0.125f, 1.0f);
    const float rh  = fmaxf(rois[r * 6 + 4] * 0.125f, 1.0f);
    const float th  = rois[r * 6 + 5];
    const int   b   = (int)b_f;

    const float st = sinf(th);
    const float ctt = cosf(th);

    const float indf   = (th * 8.0f) / 6.283185307179586f;
    const float indflo = floorf(indf);
    const float lv     = indf - indflo;
    const float rv     = 1.0f - lv;
    int ind = (int)indflo;
    ind = ((ind % 8) + 8) % 8;

    const float bin_h = rh / 7.0f;
    const float bin_w = rw / 7.0f;

    // ---- per-sample geometry ----
    if (tid < NS) {
        const int s  = tid;
        const int gx = s & 1;
        const int px = (s >> 1) % 7;
        const int gy = (s / 14) & 1;
        const int py = s / 28;

        const float yy = -rh * 0.5f + ((float)py + ((float)gy + 0.5f) * 0.5f) * bin_h;
        const float xx = -rw * 0.5f + ((float)px + ((float)gx + 0.5f) * 0.5f) * bin_w;

        const float x = xx * ctt - yy * st + cwv;
        const float y = xx * st + yy * ctt + chv;

        const bool valid = (y > -1.0f) && (y < 256.0f) && (x > -1.0f) && (x < 256.0f);

        const float yc = fmaxf(y, 0.0f);
        const float xc = fmaxf(x, 0.0f);
        int yl = (int)yc;
        int xl = (int)xc;
        int yh, xh;
        float yv, xv;
        if (yl >= HH - 1) { yl = HH - 1; yh = HH - 1; yv = (float)(HH - 1); }
        else              { yh = yl + 1;              yv = yc; }
        if (xl >= WW - 1) { xl = WW - 1; xh = WW - 1; xv = (float)(WW - 1); }
        else              { xh = xl + 1;              xv = xc; }

        const float ly = yv - (float)yl;
        const float lx = xv - (float)xl;
        const float hy = 1.0f - ly;
        const float hx = 1.0f - lx;
        const float vm = valid ? 1.0f : 0.0f;

        const int xq = xl >> 2;
        const int xr = xl & 3;

        float4 wx = make_float4(0.f, 0.f, 0.f, 0.f);
        float  we = 0.f;
        if      (xr == 0) { wx.x = hx; wx.y = lx; }
        else if (xr == 1) { wx.y = hx; wx.z = lx; }
        else if (xr == 2) { wx.z = hx; wx.w = lx; }
        else              { wx.w = hx; we   = lx; }  // tail load at xh (handles W-1 clamp too)

        sidx[s] = make_int4(yl * WW, yh * WW, xq * 4, xh);
        swx[s]  = wx;
        swy[s]  = make_float4(hy * vm, ly * vm, we, 0.f);
    }
    __syncthreads();

    const float* fb = features + ((size_t)b * CT + (size_t)cg * 8 * OO) * (size_t)HW;

    for (int cc = 0; cc < 8; ++cc) {
        const float* cb = fb + (size_t)cc * OO * HW;

        for (int it = tid; it < OO * NBIN; it += 256) {
            const int plane = it / NBIN;
            const int bin   = it - plane * NBIN;
            const int py    = bin / 7;
            const int px    = bin - py * 7;
            const float* pl = cb + plane * HW;

            float a = 0.0f;
            #pragma unroll
            for (int gy = 0; gy < 2; ++gy) {
                #pragma unroll
                for (int gx = 0; gx < 2; ++gx) {
                    const int s = ((py * 2 + gy) * 7 + px) * 2 + gx;
                    const int4   ix = sidx[s];
                    const float4 wx = swx[s];
                    const float4 wy = swy[s];

                    const float4 f0 = __ldg(reinterpret_cast<const float4*>(pl + ix.x + ix.z));
                    const float4 f1 = __ldg(reinterpret_cast<const float4*>(pl + ix.y + ix.z));

                    float d0 = f0.x * wx.x + f0.y * wx.y + f0.z * wx.z + f0.w * wx.w;
                    float d1 = f1.x * wx.x + f1.y * wx.y + f1.z * wx.z + f1.w * wx.w;

                    if (wy.z != 0.0f) {
                        d0 += wy.z * __ldg(pl + ix.x + ix.w);
                        d1 += wy.z * __ldg(pl + ix.y + ix.w);
                    }
                    a += wy.x * d0 + wy.y * d1;
                }
            }
            acc[it] = a;
        }
        __syncthreads();

        const int c = cg * 8 + cc;
        float* ob = out + ((size_t)r * CT + (size_t)c * OO) * (size_t)NBIN;
        for (int it = tid; it < OO * NBIN; it += 256) {
            const int o   = it / NBIN;
            const int bin = it - o * NBIN;
            const int p0  = (o - ind + 8) & 7;
            const int p1  = (p0 + 1) & 7;
            ob[it] = 0.25f * (rv * acc[p0 * NBIN + bin] + lv * acc[p1 * NBIN + bin]);
        }
        __syncthreads();
    }
}

extern "C" void kernel_launch(void* const* d_in, const int* in_sizes, int n_in,
                              void* d_out, int out_size)
{
    const float* features = (const float*)d_in[0];
    const float* rois     = (const float*)d_in[1];
    float*       out      = (float*)d_out;

    const int R = in_sizes[1] / 6;
    dim3 grid((unsigned)R, 4);
    riroi_kernel<<<grid, 256>>>(features, rois, out);
}